// round 6
// baseline (speedup 1.0000x reference)
#include <cuda_runtime.h>
#include <cstdint>

#define NT       4096
#define NTRACES  512
#define CHANNELS 8
#define COLS     (NTRACES * CHANNELS)   // 4096
#define THREADS  512
#define WARPS    16
#define IPT      8                      // 512*8 = 4096
#define NBINS    4096
#define CH_PER_BLK 2
#define NBLOCKS  (NTRACES * (CHANNELS / CH_PER_BLK))  // 2048

#define BIN_SCALE (4096.0f / 12.0f)

__device__ float        g_partials[NBLOCKS];
__device__ unsigned int g_done = 0;

// warpH physical slot for (bin b, warp w): 16 bytes per bin, XOR-swizzled so
// that fixed-w random-b accesses spread over 16 banks instead of 8.
// Any per-bin permutation of warp slots is fine: the cross-warp order only
// defines an arbitrary intra-bucket permutation, and the exact insertion
// cleanup re-sorts buckets by true value anyway.
__device__ __forceinline__ unsigned wh_slot(unsigned b, unsigned w) {
    return (b << 4) | ((w ^ b) & 15u);
}

// Exact counting-sort scatter of one 4096-element array (in registers) into
// buf, atomic-free. H gets this field's scanned prefix (SHIFT=0 -> low16 for
// pred, SHIFT=16 -> high16 for obs, preserving low). Block-collective.
template<int SHIFT>
__device__ __forceinline__ void phase_sort(const float* __restrict__ v,
                                           float* __restrict__ buf,
                                           unsigned* __restrict__ H,
                                           unsigned char* __restrict__ wh,
                                           int tid)
{
    __shared__ unsigned wsum_[WARPS];
    const int w = tid >> 5, lane = tid & 31;

    // ---- zero warp histograms (64KB, vectorized, conflict-free) ----
    #pragma unroll
    for (int k = 0; k < 8; ++k)
        reinterpret_cast<uint4*>(wh)[tid + k * THREADS] = make_uint4(0u,0u,0u,0u);
    __syncthreads();

    // ---- build per-warp u8 histograms; in-warp rank via match (no atomics) ----
    unsigned key[IPT];      // bin | in-warp-rank<<16
    #pragma unroll
    for (int k = 0; k < IPT; ++k) {
        int b = __float2int_rd((v[k] + 6.0f) * BIN_SCALE);
        b = min(max(b, 0), NBINS - 1);
        unsigned mask = __match_any_sync(0xFFFFFFFFu, (unsigned)b);
        int leader = __ffs(mask) - 1;
        unsigned idx = wh_slot((unsigned)b, (unsigned)w);
        unsigned old = 0;
        if (lane == leader) {
            old = wh[idx];
            wh[idx] = (unsigned char)(old + __popc(mask));
        }
        old = __shfl_sync(0xFFFFFFFFu, old, leader);
        unsigned off = old + __popc(mask & ((1u << lane) - 1u));
        key[k] = (unsigned)b | (off << 16);
    }
    __syncthreads();

    // ---- reduce: per-bin 16-byte exclusive prefix (SIMD) in place; total -> H ----
    #pragma unroll
    for (int k = 0; k < 8; ++k) {
        const int b = tid + k * THREADS;          // conflict-free vector access
        uint4 h4 = reinterpret_cast<uint4*>(wh)[b];
        unsigned p0 = h4.x * 0x01010101u;         // inclusive byte prefix / word
        unsigned p1 = h4.y * 0x01010101u;
        unsigned p2 = h4.z * 0x01010101u;
        unsigned p3 = h4.w * 0x01010101u;
        unsigned t0 = p0 >> 24, t1 = p1 >> 24, t2 = p2 >> 24;
        uint4 e;                                   // exclusive = incl - orig
        e.x = p0 - h4.x;
        e.y = (p1 - h4.y) + t0 * 0x01010101u;
        e.z = (p2 - h4.z) + (t0 + t1) * 0x01010101u;
        e.w = (p3 - h4.w) + (t0 + t1 + t2) * 0x01010101u;
        unsigned total = t0 + t1 + t2 + (p3 >> 24);
        reinterpret_cast<uint4*>(wh)[b] = e;
        if (SHIFT == 0) H[b] = total;              // clears stale high field
        else            H[b] = (H[b] & 0xFFFFu) | (total << 16);
    }
    __syncthreads();

    // ---- exclusive scan of H's SHIFT-field (8 consecutive bins / thread) ----
    {
        unsigned orig[8], loc[8];
        uint4 a = reinterpret_cast<uint4*>(H)[tid * 2];
        uint4 c = reinterpret_cast<uint4*>(H)[tid * 2 + 1];
        orig[0]=a.x; orig[1]=a.y; orig[2]=a.z; orig[3]=a.w;
        orig[4]=c.x; orig[5]=c.y; orig[6]=c.z; orig[7]=c.w;
        #pragma unroll
        for (int k = 0; k < 8; ++k) loc[k] = (orig[k] >> SHIFT) & 0xFFFFu;

        unsigned tsum = 0;
        #pragma unroll
        for (int k = 0; k < 8; ++k) { unsigned t = loc[k]; loc[k] = tsum; tsum += t; }

        unsigned x = tsum;
        #pragma unroll
        for (int off = 1; off < 32; off <<= 1) {
            unsigned y = __shfl_up_sync(0xFFFFFFFFu, x, off);
            if (lane >= off) x += y;
        }
        if (lane == 31) wsum_[w] = x;
        __syncthreads();
        if (w == 0) {
            unsigned s = (lane < WARPS) ? wsum_[lane] : 0u;
            #pragma unroll
            for (int off = 1; off < WARPS; off <<= 1) {
                unsigned y = __shfl_up_sync(0xFFFFFFFFu, s, off);
                if (lane >= off) s += y;
            }
            if (lane < WARPS) wsum_[lane] = s;
        }
        __syncthreads();
        const unsigned base = (w ? wsum_[w - 1] : 0u) + (x - tsum);
        #pragma unroll
        for (int k = 0; k < 8; ++k) loc[k] += base;

        uint4 o0, o1;
        if (SHIFT == 0) {
            o0 = make_uint4(loc[0], loc[1], loc[2], loc[3]);
            o1 = make_uint4(loc[4], loc[5], loc[6], loc[7]);
        } else {
            o0 = make_uint4((orig[0]&0xFFFFu)|(loc[0]<<16), (orig[1]&0xFFFFu)|(loc[1]<<16),
                            (orig[2]&0xFFFFu)|(loc[2]<<16), (orig[3]&0xFFFFu)|(loc[3]<<16));
            o1 = make_uint4((orig[4]&0xFFFFu)|(loc[4]<<16), (orig[5]&0xFFFFu)|(loc[5]<<16),
                            (orig[6]&0xFFFFu)|(loc[6]<<16), (orig[7]&0xFFFFu)|(loc[7]<<16));
        }
        reinterpret_cast<uint4*>(H)[tid * 2]     = o0;
        reinterpret_cast<uint4*>(H)[tid * 2 + 1] = o1;
    }
    __syncthreads();

    // ---- scatter: pos = scanned-base + cross-warp prefix + in-warp rank ----
    #pragma unroll
    for (int k = 0; k < IPT; ++k) {
        unsigned b    = key[k] & 0xFFFFu;
        unsigned base = (H[b] >> SHIFT) & 0xFFFFu;
        unsigned wpre = wh[wh_slot(b, (unsigned)w)];
        buf[base + wpre + (key[k] >> 16)] = v[k];
    }
    __syncthreads();
}

// Dynamic smem: bufP 16K | bufO 16K | H 16K | warpH 64K  = 112KB
__global__ __launch_bounds__(THREADS, 2)
void wass_nomic_kernel(const float* __restrict__ pred,
                       const float* __restrict__ obs,
                       float* __restrict__ out)
{
    extern __shared__ float smem[];
    float*         bufP = smem;
    float*         bufO = smem + 4096;
    unsigned*      H    = reinterpret_cast<unsigned*>(smem + 8192);
    unsigned char* wh   = reinterpret_cast<unsigned char*>(smem + 12288);

    __shared__ float  sred[WARPS];
    __shared__ double dred[WARPS];
    __shared__ bool   s_last;

    const int tid  = threadIdx.x;
    const int tr   = blockIdx.x >> 2;
    const int c0   = (blockIdx.x & 3) * CH_PER_BLK;
    const int base = tr * CHANNELS + c0;
    const int wid  = tid >> 5;
    const int lane = tid & 31;

    float acc = 0.0f;

    #pragma unroll 1          // force re-load per pair (keeps regs <= 64)
    for (int p = 0; p < CH_PER_BLK; ++p) {
        float vp[IPT], vo[IPT];
        #pragma unroll
        for (int k = 0; k < IPT; ++k) {
            const int t = tid + k * THREADS;
            const size_t off = (size_t)t * COLS + base;
            float2 pp = *reinterpret_cast<const float2*>(pred + off);
            float2 oo = *reinterpret_cast<const float2*>(obs  + off);
            vp[k] = p ? pp.y : pp.x;
            vo[k] = p ? oo.y : oo.x;
        }

        phase_sort<0 >(vp, bufP, H, wh, tid);
        phase_sort<16>(vo, bufO, H, wh, tid);

        // ---- exact within-bucket insertion cleanup ----
        #pragma unroll 1
        for (int b = tid; b < NBINS; b += THREADS) {
            const unsigned E0 = H[b];
            const unsigned E1 = (b < NBINS - 1) ? H[b + 1]
                                                : ((unsigned)NT | ((unsigned)NT << 16));
            const int sP = (int)(E0 & 0xFFFFu), eP = (int)(E1 & 0xFFFFu);
            const int sO = (int)(E0 >> 16),     eO = (int)(E1 >> 16);

            for (int i = sP + 1; i < eP; ++i) {
                float v = bufP[i]; int j = i - 1;
                while (j >= sP && bufP[j] > v) { bufP[j + 1] = bufP[j]; --j; }
                bufP[j + 1] = v;
            }
            for (int i = sO + 1; i < eO; ++i) {
                float v = bufO[i]; int j = i - 1;
                while (j >= sO && bufO[j] > v) { bufO[j + 1] = bufO[j]; --j; }
                bufO[j + 1] = v;
            }
        }
        __syncthreads();

        // ---- coherent vectorized diff ----
        {
            const float4* P4 = reinterpret_cast<const float4*>(bufP) + tid * 2;
            const float4* O4 = reinterpret_cast<const float4*>(bufO) + tid * 2;
            #pragma unroll
            for (int k = 0; k < 2; ++k) {
                float4 a = P4[k], c = O4[k];
                acc += fabsf(a.x - c.x) + fabsf(a.y - c.y)
                     + fabsf(a.z - c.z) + fabsf(a.w - c.w);
            }
        }
        __syncthreads();   // buffers/H reused by next pair
    }

    // ---- deterministic block reduction ----
    #pragma unroll
    for (int off = 16; off > 0; off >>= 1)
        acc += __shfl_xor_sync(0xFFFFFFFFu, acc, off);
    if (lane == 0) sred[wid] = acc;
    __syncthreads();

    if (wid == 0) {
        float v = (lane < WARPS) ? sred[lane] : 0.0f;
        #pragma unroll
        for (int off = 8; off > 0; off >>= 1)
            v += __shfl_xor_sync(0xFFFFFFFFu, v, off);
        if (lane == 0) g_partials[blockIdx.x] = v;
    }

    // ---- last-block-done fused finalize (deterministic) ----
    if (tid == 0) {
        __threadfence();
        unsigned int t = atomicAdd(&g_done, 1u);
        s_last = (t == NBLOCKS - 1);
    }
    __syncthreads();

    if (s_last) {
        __threadfence();
        double d = 0.0;
        for (int i = tid; i < NBLOCKS; i += THREADS)
            d += (double)g_partials[i];
        #pragma unroll
        for (int off = 16; off > 0; off >>= 1)
            d += __shfl_xor_sync(0xFFFFFFFFu, d, off);
        if (lane == 0) dred[wid] = d;
        __syncthreads();
        if (wid == 0) {
            double v = (lane < WARPS) ? dred[lane] : 0.0;
            #pragma unroll
            for (int off = 8; off > 0; off >>= 1)
                v += __shfl_xor_sync(0xFFFFFFFFu, v, off);
            if (lane == 0) {
                out[0] = (float)(v / ((double)NT * (double)COLS));
                g_done = 0;   // reset for next graph replay
            }
        }
    }
}

extern "C" void kernel_launch(void* const* d_in, const int* in_sizes, int n_in,
                              void* d_out, int out_size)
{
    const float* pred = (const float*)d_in[0];
    const float* obs  = (const float*)d_in[1];
    float* out = (float*)d_out;

    const size_t smem_bytes = (3 * 4096) * sizeof(float) + NBINS * 16;  // 112KB
    cudaFuncSetAttribute(wass_nomic_kernel,
                         cudaFuncAttributeMaxDynamicSharedMemorySize,
                         (int)smem_bytes);

    wass_nomic_kernel<<<NBLOCKS, THREADS, smem_bytes>>>(pred, obs, out);
}

// round 7
// speedup vs baseline: 1.4144x; 1.4144x over previous
#include <cuda_runtime.h>
#include <cstdint>

#define NT       4096
#define NTRACES  512
#define CHANNELS 8
#define COLS     (NTRACES * CHANNELS)   // 4096
#define THREADS  512
#define WARPS    16
#define IPT      8                      // 512*8 = 4096
#define NBINS    4096
#define NBLOCKS  COLS                   // one (trace, channel) column pair per block

#define BIN_SCALE (4096.0f / 12.0f)

__device__ float        g_partials[NBLOCKS];
__device__ unsigned int g_done = 0;

// Dynamic smem: bufP 16K | bufO 16K | H 16K = 48KB  -> 4 blocks/SM
__global__ __launch_bounds__(THREADS, 4)
void wass_occ_kernel(const float* __restrict__ pred,
                     const float* __restrict__ obs,
                     float* __restrict__ out)
{
    extern __shared__ float smem[];
    float*    bufP = smem;
    float*    bufO = smem + 4096;
    unsigned* H    = reinterpret_cast<unsigned*>(smem + 8192);

    __shared__ unsigned wsum[WARPS];
    __shared__ float    sred[WARPS];
    __shared__ double   dred[WARPS];
    __shared__ bool     s_last;

    const int tid  = threadIdx.x;
    const int lane = tid & 31;
    const int wid  = tid >> 5;
    // consecutive blocks = consecutive channels of one trace -> co-resident,
    // their stride-COLS scalar loads share 32B sectors via L2 dedup.
    const int col  = blockIdx.x;   // tr*CHANNELS + ch

    // ---- load column into registers (scalar, L2-dedup across sibling blocks) ----
    float vp[IPT], vo[IPT];
    #pragma unroll
    for (int k = 0; k < IPT; ++k) {
        const size_t off = (size_t)(tid + k * THREADS) * COLS + col;
        vp[k] = __ldg(pred + off);
        vo[k] = __ldg(obs  + off);
    }

    // ---- zero packed histogram (vectorized) ----
    {
        uint4 z = make_uint4(0u, 0u, 0u, 0u);
        reinterpret_cast<uint4*>(H)[tid]           = z;
        reinterpret_cast<uint4*>(H)[tid + THREADS] = z;
    }
    __syncthreads();

    // ---- histogram; atomic returns intra-bucket rank (kept in regs) ----
    unsigned pk[IPT], ok[IPT];   // bin | rank<<16
    #pragma unroll
    for (int k = 0; k < IPT; ++k) {
        int b = __float2int_rd((vp[k] + 6.0f) * BIN_SCALE);
        b = min(max(b, 0), NBINS - 1);
        unsigned r = atomicAdd(&H[b], 1u) & 0xFFFFu;
        pk[k] = (unsigned)b | (r << 16);
    }
    #pragma unroll
    for (int k = 0; k < IPT; ++k) {
        int b = __float2int_rd((vo[k] + 6.0f) * BIN_SCALE);
        b = min(max(b, 0), NBINS - 1);
        unsigned r = atomicAdd(&H[b], 0x10000u) >> 16;
        ok[k] = (unsigned)b | (r << 16);
    }
    __syncthreads();

    // ---- packed exclusive scan of H in place (both 16-bit fields at once) ----
    {
        unsigned loc[8];
        uint4 h0 = reinterpret_cast<uint4*>(H)[tid * 2];
        uint4 h1 = reinterpret_cast<uint4*>(H)[tid * 2 + 1];
        loc[0] = h0.x; loc[1] = h0.y; loc[2] = h0.z; loc[3] = h0.w;
        loc[4] = h1.x; loc[5] = h1.y; loc[6] = h1.z; loc[7] = h1.w;

        unsigned tsum = 0;
        #pragma unroll
        for (int k = 0; k < 8; ++k) { unsigned t = loc[k]; loc[k] = tsum; tsum += t; }

        unsigned x = tsum;
        #pragma unroll
        for (int off = 1; off < 32; off <<= 1) {
            unsigned y = __shfl_up_sync(0xFFFFFFFFu, x, off);
            if (lane >= off) x += y;
        }
        if (lane == 31) wsum[wid] = x;
        __syncthreads();
        if (wid == 0) {
            unsigned w = (lane < WARPS) ? wsum[lane] : 0u;
            #pragma unroll
            for (int off = 1; off < WARPS; off <<= 1) {
                unsigned y = __shfl_up_sync(0xFFFFFFFFu, w, off);
                if (lane >= off) w += y;
            }
            if (lane < WARPS) wsum[lane] = w;
        }
        __syncthreads();
        const unsigned base = (wid ? wsum[wid - 1] : 0u) + (x - tsum);
        #pragma unroll
        for (int k = 0; k < 8; ++k) loc[k] += base;
        reinterpret_cast<uint4*>(H)[tid * 2]     = make_uint4(loc[0], loc[1], loc[2], loc[3]);
        reinterpret_cast<uint4*>(H)[tid * 2 + 1] = make_uint4(loc[4], loc[5], loc[6], loc[7]);
    }
    __syncthreads();

    // ---- scatter (no atomics: prefix + saved rank) ----
    #pragma unroll
    for (int k = 0; k < IPT; ++k) {
        unsigned b = pk[k] & 0xFFFFu, r = pk[k] >> 16;
        bufP[(H[b] & 0xFFFFu) + r] = vp[k];
    }
    #pragma unroll
    for (int k = 0; k < IPT; ++k) {
        unsigned b = ok[k] & 0xFFFFu, r = ok[k] >> 16;
        bufO[(H[b] >> 16) + r] = vo[k];
    }
    __syncthreads();

    // ---- exact within-bucket insertion cleanup (avg ~1 element/bucket) ----
    #pragma unroll 1
    for (int b = tid; b < NBINS; b += THREADS) {
        const unsigned E0 = H[b];
        const unsigned E1 = (b < NBINS - 1) ? H[b + 1]
                                            : ((unsigned)NT | ((unsigned)NT << 16));
        const int sP = (int)(E0 & 0xFFFFu), eP = (int)(E1 & 0xFFFFu);
        const int sO = (int)(E0 >> 16),     eO = (int)(E1 >> 16);

        for (int i = sP + 1; i < eP; ++i) {
            float v = bufP[i]; int j = i - 1;
            while (j >= sP && bufP[j] > v) { bufP[j + 1] = bufP[j]; --j; }
            bufP[j + 1] = v;
        }
        for (int i = sO + 1; i < eO; ++i) {
            float v = bufO[i]; int j = i - 1;
            while (j >= sO && bufO[j] > v) { bufO[j + 1] = bufO[j]; --j; }
            bufO[j + 1] = v;
        }
    }
    __syncthreads();

    // ---- coherent vectorized diff: contiguous 8 elements per thread ----
    float acc = 0.0f;
    {
        const float4* P4 = reinterpret_cast<const float4*>(bufP) + tid * 2;
        const float4* O4 = reinterpret_cast<const float4*>(bufO) + tid * 2;
        #pragma unroll
        for (int k = 0; k < 2; ++k) {
            float4 a = P4[k], c = O4[k];
            acc += fabsf(a.x - c.x) + fabsf(a.y - c.y)
                 + fabsf(a.z - c.z) + fabsf(a.w - c.w);
        }
    }

    // ---- deterministic block reduction ----
    #pragma unroll
    for (int off = 16; off > 0; off >>= 1)
        acc += __shfl_xor_sync(0xFFFFFFFFu, acc, off);
    if (lane == 0) sred[wid] = acc;
    __syncthreads();

    if (wid == 0) {
        float v = (lane < WARPS) ? sred[lane] : 0.0f;
        #pragma unroll
        for (int off = 8; off > 0; off >>= 1)
            v += __shfl_xor_sync(0xFFFFFFFFu, v, off);
        if (lane == 0) g_partials[blockIdx.x] = v;
    }

    // ---- last-block-done fused finalize (deterministic) ----
    if (tid == 0) {
        __threadfence();
        unsigned int t = atomicAdd(&g_done, 1u);
        s_last = (t == NBLOCKS - 1);
    }
    __syncthreads();

    if (s_last) {
        __threadfence();
        double d = 0.0;
        for (int i = tid; i < NBLOCKS; i += THREADS)
            d += (double)g_partials[i];
        #pragma unroll
        for (int off = 16; off > 0; off >>= 1)
            d += __shfl_xor_sync(0xFFFFFFFFu, d, off);
        if (lane == 0) dred[wid] = d;
        __syncthreads();
        if (wid == 0) {
            double v = (lane < WARPS) ? dred[lane] : 0.0;
            #pragma unroll
            for (int off = 8; off > 0; off >>= 1)
                v += __shfl_xor_sync(0xFFFFFFFFu, v, off);
            if (lane == 0) {
                out[0] = (float)(v / ((double)NT * (double)COLS));
                g_done = 0;   // reset for next graph replay
            }
        }
    }
}

extern "C" void kernel_launch(void* const* d_in, const int* in_sizes, int n_in,
                              void* d_out, int out_size)
{
    const float* pred = (const float*)d_in[0];
    const float* obs  = (const float*)d_in[1];
    float* out = (float*)d_out;

    const size_t smem_bytes = 3 * 4096 * sizeof(float);   // 48KB
    cudaFuncSetAttribute(wass_occ_kernel,
                         cudaFuncAttributeMaxDynamicSharedMemorySize,
                         (int)smem_bytes);

    wass_occ_kernel<<<NBLOCKS, THREADS, smem_bytes>>>(pred, obs, out);
}

// round 8
// speedup vs baseline: 1.7740x; 1.2543x over previous
#include <cuda_runtime.h>
#include <cstdint>

#define NT       4096
#define NTRACES  512
#define CHANNELS 8
#define COLS     (NTRACES * CHANNELS)   // 4096
#define THREADS  512
#define WARPS    16
#define IPT      8                      // 512*8 = 4096
#define NBINS    4096
#define CH_PER_BLK 2
#define NBLOCKS  (NTRACES * (CHANNELS / CH_PER_BLK))  // 2048

#define BIN_SCALE (4096.0f / 12.0f)

__device__ float        g_partials[NBLOCKS];
__device__ unsigned int g_done = 0;
// Per-block global histogram scratch (obs ranks go through L2 atomics).
// Static __device__ array: no allocation. 2048 * 4096 * 4B = 32MB.
__device__ unsigned     g_hist[NBLOCKS * NBINS];

// One (pred,obs) column pair, inputs in registers. Exact counting sort of both
// into bufP/bufO. Pred ranks: smem ATOMS on H. Obs ranks: global ATOMG on gH
// (different HW unit -> runs in parallel with ATOMS). Block-collective.
__device__ __forceinline__ float process_pair(const float* __restrict__ vp,
                                               const float* __restrict__ vo,
                                               float* __restrict__ bufP,
                                               float* __restrict__ bufO,
                                               unsigned* __restrict__ H,
                                               unsigned* __restrict__ gH,
                                               int tid)
{
    __shared__ unsigned wsum[WARPS];
    const int lane = tid & 31, w = tid >> 5;

    // ---- zero smem H and this block's global scratch slice ----
    {
        uint4 z = make_uint4(0u, 0u, 0u, 0u);
        reinterpret_cast<uint4*>(H)[tid]            = z;
        reinterpret_cast<uint4*>(H)[tid + THREADS]  = z;
        reinterpret_cast<uint4*>(gH)[tid]           = z;
        reinterpret_cast<uint4*>(gH)[tid + THREADS] = z;
    }
    __syncthreads();   // zeros visible block-wide (global+shared) before atomics

    // ---- obs: global atomics first (L2 unit; latency hidden by pred ATOMS) ----
    unsigned ok[IPT];   // bin | rank<<16
    #pragma unroll
    for (int k = 0; k < IPT; ++k) {
        int b = __float2int_rd((vo[k] + 6.0f) * BIN_SCALE);
        b = min(max(b, 0), NBINS - 1);
        unsigned r = atomicAdd(&gH[b], 1u);
        ok[k] = (unsigned)b | (r << 16);
    }

    // ---- pred: smem atomics (ATOMS unit), returns intra-bucket rank ----
    unsigned pk[IPT];   // bin | rank<<16
    #pragma unroll
    for (int k = 0; k < IPT; ++k) {
        int b = __float2int_rd((vp[k] + 6.0f) * BIN_SCALE);
        b = min(max(b, 0), NBINS - 1);
        unsigned r = atomicAdd(&H[b], 1u) & 0xFFFFu;
        pk[k] = (unsigned)b | (r << 16);
    }
    __syncthreads();   // all atomics done; counts stable

    // ---- pack (predCount | obsCount<<16), exclusive scan in place ----
    {
        unsigned loc[8];
        {
            uint4 a = reinterpret_cast<uint4*>(H)[tid * 2];
            uint4 c = reinterpret_cast<uint4*>(H)[tid * 2 + 1];
            // obs counts: L1-bypassing loads (atomics completed at L2)
            uint4 g0 = __ldcg(reinterpret_cast<const uint4*>(gH) + tid * 2);
            uint4 g1 = __ldcg(reinterpret_cast<const uint4*>(gH) + tid * 2 + 1);
            loc[0] = a.x | (g0.x << 16); loc[1] = a.y | (g0.y << 16);
            loc[2] = a.z | (g0.z << 16); loc[3] = a.w | (g0.w << 16);
            loc[4] = c.x | (g1.x << 16); loc[5] = c.y | (g1.y << 16);
            loc[6] = c.z | (g1.z << 16); loc[7] = c.w | (g1.w << 16);
        }

        unsigned tsum = 0;
        #pragma unroll
        for (int k = 0; k < 8; ++k) { unsigned t = loc[k]; loc[k] = tsum; tsum += t; }

        unsigned x = tsum;
        #pragma unroll
        for (int off = 1; off < 32; off <<= 1) {
            unsigned y = __shfl_up_sync(0xFFFFFFFFu, x, off);
            if (lane >= off) x += y;
        }
        if (lane == 31) wsum[w] = x;
        __syncthreads();
        if (w == 0) {
            unsigned s = (lane < WARPS) ? wsum[lane] : 0u;
            #pragma unroll
            for (int off = 1; off < WARPS; off <<= 1) {
                unsigned y = __shfl_up_sync(0xFFFFFFFFu, s, off);
                if (lane >= off) s += y;
            }
            if (lane < WARPS) wsum[lane] = s;
        }
        __syncthreads();
        const unsigned base = (w ? wsum[w - 1] : 0u) + (x - tsum);
        #pragma unroll
        for (int k = 0; k < 8; ++k) loc[k] += base;
        reinterpret_cast<uint4*>(H)[tid * 2]     = make_uint4(loc[0], loc[1], loc[2], loc[3]);
        reinterpret_cast<uint4*>(H)[tid * 2 + 1] = make_uint4(loc[4], loc[5], loc[6], loc[7]);
    }
    __syncthreads();

    // ---- scatter (no atomics: prefix + saved rank) ----
    #pragma unroll
    for (int k = 0; k < IPT; ++k) {
        unsigned b = pk[k] & 0xFFFFu, r = pk[k] >> 16;
        bufP[(H[b] & 0xFFFFu) + r] = vp[k];
    }
    #pragma unroll
    for (int k = 0; k < IPT; ++k) {
        unsigned b = ok[k] & 0xFFFFu, r = ok[k] >> 16;
        bufO[(H[b] >> 16) + r] = vo[k];
    }
    __syncthreads();

    // ---- exact within-bucket insertion cleanup (avg ~1 element/bucket) ----
    #pragma unroll 1
    for (int b = tid; b < NBINS; b += THREADS) {
        const unsigned E0 = H[b];
        const unsigned E1 = (b < NBINS - 1) ? H[b + 1]
                                            : ((unsigned)NT | ((unsigned)NT << 16));
        const int sP = (int)(E0 & 0xFFFFu), eP = (int)(E1 & 0xFFFFu);
        const int sO = (int)(E0 >> 16),     eO = (int)(E1 >> 16);

        for (int i = sP + 1; i < eP; ++i) {
            float v = bufP[i]; int j = i - 1;
            while (j >= sP && bufP[j] > v) { bufP[j + 1] = bufP[j]; --j; }
            bufP[j + 1] = v;
        }
        for (int i = sO + 1; i < eO; ++i) {
            float v = bufO[i]; int j = i - 1;
            while (j >= sO && bufO[j] > v) { bufO[j + 1] = bufO[j]; --j; }
            bufO[j + 1] = v;
        }
    }
    __syncthreads();

    // ---- coherent vectorized diff: contiguous 8 elements per thread ----
    float acc = 0.0f;
    {
        const float4* P4 = reinterpret_cast<const float4*>(bufP) + tid * 2;
        const float4* O4 = reinterpret_cast<const float4*>(bufO) + tid * 2;
        #pragma unroll
        for (int k = 0; k < 2; ++k) {
            float4 a = P4[k], c = O4[k];
            acc += fabsf(a.x - c.x) + fabsf(a.y - c.y)
                 + fabsf(a.z - c.z) + fabsf(a.w - c.w);
        }
    }
    __syncthreads();   // buffers/H reused by next pair
    return acc;
}

// Dynamic smem: bufP, bufO, H, stageP, stageO -> 5 * 16KB = 80KB
__global__ __launch_bounds__(THREADS, 2)
void wass_split_kernel(const float* __restrict__ pred,
                       const float* __restrict__ obs,
                       float* __restrict__ out)
{
    extern __shared__ float smem[];
    float*    bufP   = smem;
    float*    bufO   = smem + 4096;
    unsigned* H      = reinterpret_cast<unsigned*>(smem + 8192);
    float*    stageP = smem + 12288;
    float*    stageO = smem + 16384;
    unsigned* gH     = g_hist + (size_t)blockIdx.x * NBINS;

    __shared__ float  sred[WARPS];
    __shared__ double dred[WARPS];
    __shared__ bool   s_last;

    const int tid  = threadIdx.x;
    const int tr   = blockIdx.x >> 2;
    const int c0   = (blockIdx.x & 3) * CH_PER_BLK;
    const int base = tr * CHANNELS + c0;

    // ---- load: float2 over 2 adjacent channels (L2 dedups 32B sectors).
    // ch0 -> registers, ch1 -> thread-private smem staging (no sync needed).
    float vp[IPT], vo[IPT];
    #pragma unroll
    for (int k = 0; k < IPT; ++k) {
        const int t = tid + k * THREADS;
        const size_t off = (size_t)t * COLS + base;
        float2 p = *reinterpret_cast<const float2*>(pred + off);
        float2 o = *reinterpret_cast<const float2*>(obs  + off);
        vp[k] = p.x; vo[k] = o.x;
        stageP[t] = p.y; stageO[t] = o.y;
    }

    float acc = process_pair(vp, vo, bufP, bufO, H, gH, tid);

    #pragma unroll
    for (int k = 0; k < IPT; ++k) {
        const int t = tid + k * THREADS;
        vp[k] = stageP[t]; vo[k] = stageO[t];
    }
    acc += process_pair(vp, vo, bufP, bufO, H, gH, tid);

    // ---- deterministic block reduction ----
    #pragma unroll
    for (int off = 16; off > 0; off >>= 1)
        acc += __shfl_xor_sync(0xFFFFFFFFu, acc, off);

    const int wid  = tid >> 5;
    const int lane = tid & 31;
    if (lane == 0) sred[wid] = acc;
    __syncthreads();

    if (wid == 0) {
        float v = (lane < WARPS) ? sred[lane] : 0.0f;
        #pragma unroll
        for (int off = 8; off > 0; off >>= 1)
            v += __shfl_xor_sync(0xFFFFFFFFu, v, off);
        if (lane == 0) g_partials[blockIdx.x] = v;
    }

    // ---- last-block-done fused finalize (deterministic) ----
    if (tid == 0) {
        __threadfence();
        unsigned int t = atomicAdd(&g_done, 1u);
        s_last = (t == NBLOCKS - 1);
    }
    __syncthreads();

    if (s_last) {
        __threadfence();
        double d = 0.0;
        for (int i = tid; i < NBLOCKS; i += THREADS)
            d += (double)g_partials[i];
        #pragma unroll
        for (int off = 16; off > 0; off >>= 1)
            d += __shfl_xor_sync(0xFFFFFFFFu, d, off);
        if (lane == 0) dred[wid] = d;
        __syncthreads();
        if (wid == 0) {
            double v = (lane < WARPS) ? dred[lane] : 0.0;
            #pragma unroll
            for (int off = 8; off > 0; off >>= 1)
                v += __shfl_xor_sync(0xFFFFFFFFu, v, off);
            if (lane == 0) {
                out[0] = (float)(v / ((double)NT * (double)COLS));
                g_done = 0;   // reset for next graph replay
            }
        }
    }
}

extern "C" void kernel_launch(void* const* d_in, const int* in_sizes, int n_in,
                              void* d_out, int out_size)
{
    const float* pred = (const float*)d_in[0];
    const float* obs  = (const float*)d_in[1];
    float* out = (float*)d_out;

    const size_t smem_bytes = 5 * 4096 * sizeof(float);   // 80KB
    cudaFuncSetAttribute(wass_split_kernel,
                         cudaFuncAttributeMaxDynamicSharedMemorySize,
                         (int)smem_bytes);

    wass_split_kernel<<<NBLOCKS, THREADS, smem_bytes>>>(pred, obs, out);
}

// round 9
// speedup vs baseline: 1.8076x; 1.0190x over previous
#include <cuda_runtime.h>
#include <cstdint>

#define NT       4096
#define NTRACES  512
#define CHANNELS 8
#define COLS     (NTRACES * CHANNELS)   // 4096
#define THREADS  512
#define WARPS    16
#define IPT      8                      // 512*8 = 4096
#define NBINS    4096
#define CH_PER_BLK 2
#define NBLOCKS  (NTRACES * (CHANNELS / CH_PER_BLK))  // 2048

#define BIN_SCALE (4096.0f / 12.0f)

__device__ float        g_partials[NBLOCKS];
__device__ unsigned int g_done = 0;

__device__ __forceinline__ int bin_of(float v) {
    int b = __float2int_rd(fmaf(v, BIN_SCALE, 6.0f * BIN_SCALE));
    return min(max(b, 0), NBINS - 1);
}

// Dynamic smem: bufP 16K | bufO 16K | H 16K = 48KB
__global__ __launch_bounds__(THREADS, 2)
void wass_v9_kernel(const float* __restrict__ pred,
                    const float* __restrict__ obs,
                    float* __restrict__ out)
{
    extern __shared__ float smem[];
    float*    bufP = smem;
    float*    bufO = smem + 4096;
    unsigned* H    = reinterpret_cast<unsigned*>(smem + 8192);

    __shared__ unsigned wsum[WARPS];
    __shared__ float    sred[WARPS];
    __shared__ double   dred[WARPS];
    __shared__ bool     s_last;

    const int tid  = threadIdx.x;
    const int lane = tid & 31;
    const int wid  = tid >> 5;
    const int tr   = blockIdx.x >> 2;
    const int c0   = (blockIdx.x & 3) * CH_PER_BLK;
    const int base = tr * CHANNELS + c0;

    float acc = 0.0f;

    // ---- initial H zero (pair 1's zero overlaps pair 0's diff phase) ----
    {
        uint4 z = make_uint4(0u, 0u, 0u, 0u);
        reinterpret_cast<uint4*>(H)[tid]           = z;
        reinterpret_cast<uint4*>(H)[tid + THREADS] = z;
    }
    __syncthreads();

    #pragma unroll 1
    for (int p = 0; p < CH_PER_BLK; ++p) {
        // ---- load this pair: float2 (L2 dedups sectors; pair 1 reload is L2-hot)
        float vp[IPT], vo[IPT];
        #pragma unroll
        for (int k = 0; k < IPT; ++k) {
            const size_t off = (size_t)(tid + k * THREADS) * COLS + base;
            float2 pp = __ldg(reinterpret_cast<const float2*>(pred + off));
            float2 oo = __ldg(reinterpret_cast<const float2*>(obs  + off));
            vp[k] = p ? pp.y : pp.x;
            vo[k] = p ? oo.y : oo.x;
        }

        // ---- histogram: interleaved pred/obs atomics (rank = returned count) ----
        unsigned pk[IPT], ok[IPT];   // bin | rank<<16
        #pragma unroll
        for (int k = 0; k < IPT; ++k) {
            int bp = bin_of(vp[k]);
            int bo = bin_of(vo[k]);
            unsigned rp = atomicAdd(&H[bp], 1u) & 0xFFFFu;
            unsigned ro = atomicAdd(&H[bo], 0x10000u) >> 16;
            pk[k] = (unsigned)bp | (rp << 16);
            ok[k] = (unsigned)bo | (ro << 16);
        }
        __syncthreads();

        // ---- packed exclusive scan of H in place (both 16-bit fields) ----
        {
            unsigned loc[8];
            uint4 h0 = reinterpret_cast<uint4*>(H)[tid * 2];
            uint4 h1 = reinterpret_cast<uint4*>(H)[tid * 2 + 1];
            loc[0]=h0.x; loc[1]=h0.y; loc[2]=h0.z; loc[3]=h0.w;
            loc[4]=h1.x; loc[5]=h1.y; loc[6]=h1.z; loc[7]=h1.w;

            unsigned tsum = 0;
            #pragma unroll
            for (int k = 0; k < 8; ++k) { unsigned t = loc[k]; loc[k] = tsum; tsum += t; }

            unsigned x = tsum;
            #pragma unroll
            for (int off = 1; off < 32; off <<= 1) {
                unsigned y = __shfl_up_sync(0xFFFFFFFFu, x, off);
                if (lane >= off) x += y;
            }
            if (lane == 31) wsum[wid] = x;
            __syncthreads();
            if (wid == 0) {
                unsigned s = (lane < WARPS) ? wsum[lane] : 0u;
                #pragma unroll
                for (int off = 1; off < WARPS; off <<= 1) {
                    unsigned y = __shfl_up_sync(0xFFFFFFFFu, s, off);
                    if (lane >= off) s += y;
                }
                if (lane < WARPS) wsum[lane] = s;
            }
            __syncthreads();
            const unsigned bse = (wid ? wsum[wid - 1] : 0u) + (x - tsum);
            #pragma unroll
            for (int k = 0; k < 8; ++k) loc[k] += bse;
            reinterpret_cast<uint4*>(H)[tid * 2]     = make_uint4(loc[0], loc[1], loc[2], loc[3]);
            reinterpret_cast<uint4*>(H)[tid * 2 + 1] = make_uint4(loc[4], loc[5], loc[6], loc[7]);
        }
        __syncthreads();

        // ---- scatter (no atomics: prefix + saved rank) ----
        #pragma unroll
        for (int k = 0; k < IPT; ++k) {
            unsigned b = pk[k] & 0xFFFFu, r = pk[k] >> 16;
            bufP[(H[b] & 0xFFFFu) + r] = vp[k];
        }
        #pragma unroll
        for (int k = 0; k < IPT; ++k) {
            unsigned b = ok[k] & 0xFFFFu, r = ok[k] >> 16;
            bufO[(H[b] >> 16) + r] = vo[k];
        }
        __syncthreads();

        // ---- exact within-bucket insertion cleanup (avg ~1 elem/bucket) ----
        #pragma unroll 1
        for (int b = tid; b < NBINS; b += THREADS) {
            const unsigned E0 = H[b];
            const unsigned E1 = (b < NBINS - 1) ? H[b + 1]
                                                : ((unsigned)NT | ((unsigned)NT << 16));
            const int sP = (int)(E0 & 0xFFFFu), eP = (int)(E1 & 0xFFFFu);
            const int sO = (int)(E0 >> 16),     eO = (int)(E1 >> 16);

            for (int i = sP + 1; i < eP; ++i) {
                float v = bufP[i]; int j = i - 1;
                while (j >= sP && bufP[j] > v) { bufP[j + 1] = bufP[j]; --j; }
                bufP[j + 1] = v;
            }
            for (int i = sO + 1; i < eO; ++i) {
                float v = bufO[i]; int j = i - 1;
                while (j >= sO && bufO[j] > v) { bufO[j + 1] = bufO[j]; --j; }
                bufO[j + 1] = v;
            }
        }
        __syncthreads();

        // ---- diff (coherent float4) + overlap: zero H for the next pair ----
        {
            const float4* P4 = reinterpret_cast<const float4*>(bufP) + tid * 2;
            const float4* O4 = reinterpret_cast<const float4*>(bufO) + tid * 2;
            #pragma unroll
            for (int k = 0; k < 2; ++k) {
                float4 a = P4[k], c = O4[k];
                acc += fabsf(a.x - c.x) + fabsf(a.y - c.y)
                     + fabsf(a.z - c.z) + fabsf(a.w - c.w);
            }
            uint4 z = make_uint4(0u, 0u, 0u, 0u);
            reinterpret_cast<uint4*>(H)[tid]           = z;
            reinterpret_cast<uint4*>(H)[tid + THREADS] = z;
        }
        __syncthreads();   // buffers/H ready for next pair
    }

    // ---- deterministic block reduction ----
    #pragma unroll
    for (int off = 16; off > 0; off >>= 1)
        acc += __shfl_xor_sync(0xFFFFFFFFu, acc, off);
    if (lane == 0) sred[wid] = acc;
    __syncthreads();

    if (wid == 0) {
        float v = (lane < WARPS) ? sred[lane] : 0.0f;
        #pragma unroll
        for (int off = 8; off > 0; off >>= 1)
            v += __shfl_xor_sync(0xFFFFFFFFu, v, off);
        if (lane == 0) g_partials[blockIdx.x] = v;
    }

    // ---- last-block-done fused finalize (deterministic) ----
    if (tid == 0) {
        __threadfence();
        unsigned int t = atomicAdd(&g_done, 1u);
        s_last = (t == NBLOCKS - 1);
    }
    __syncthreads();

    if (s_last) {
        __threadfence();
        double d = 0.0;
        for (int i = tid; i < NBLOCKS; i += THREADS)
            d += (double)g_partials[i];
        #pragma unroll
        for (int off = 16; off > 0; off >>= 1)
            d += __shfl_xor_sync(0xFFFFFFFFu, d, off);
        if (lane == 0) dred[wid] = d;
        __syncthreads();
        if (wid == 0) {
            double v = (lane < WARPS) ? dred[lane] : 0.0;
            #pragma unroll
            for (int off = 8; off > 0; off >>= 1)
                v += __shfl_xor_sync(0xFFFFFFFFu, v, off);
            if (lane == 0) {
                out[0] = (float)(v / ((double)NT * (double)COLS));
                g_done = 0;   // reset for next graph replay
            }
        }
    }
}

extern "C" void kernel_launch(void* const* d_in, const int* in_sizes, int n_in,
                              void* d_out, int out_size)
{
    const float* pred = (const float*)d_in[0];
    const float* obs  = (const float*)d_in[1];
    float* out = (float*)d_out;

    const size_t smem_bytes = 3 * 4096 * sizeof(float);   // 48KB
    cudaFuncSetAttribute(wass_v9_kernel,
                         cudaFuncAttributeMaxDynamicSharedMemorySize,
                         (int)smem_bytes);

    wass_v9_kernel<<<NBLOCKS, THREADS, smem_bytes>>>(pred, obs, out);
}